// round 1
// baseline (speedup 1.0000x reference)
#include <cuda_runtime.h>
#include <cstdint>
#include <cstddef>

// MOELinearB: out[t,e,o] = sum_r x[t, e*128+r] * W[e,o,r]
// x: [T, 8*128] fp32, W: [8, 4096, 128] fp32, out: [T, 8, 4096] fp32
//
// Per-expert GEMM: M=T (8192), N=4096, K=128.
// CTA tile: 128(M) x 128(N), full K=128 in smem (single-shot, no k-pipeline).
// 8 warps = 4(M) x 2(N); warp tile 32x64 via mma.sync.m16n8k8 TF32.

#define EXPERTS 8
#define RANK    128
#define OUTF    4096
#define BM      128
#define BN      128

__device__ __forceinline__ float tf32r(float f) {
    uint32_t u;
    asm("cvt.rna.tf32.f32 %0, %1;" : "=r"(u) : "f"(f));
    return __uint_as_float(u);
}

__device__ __forceinline__ void mma_tf32(float c[4], const uint32_t a[4], const uint32_t b[2]) {
    asm volatile(
        "mma.sync.aligned.m16n8k8.row.col.f32.tf32.tf32.f32 "
        "{%0,%1,%2,%3}, {%4,%5,%6,%7}, {%8,%9}, {%0,%1,%2,%3};"
        : "+f"(c[0]), "+f"(c[1]), "+f"(c[2]), "+f"(c[3])
        : "r"(a[0]), "r"(a[1]), "r"(a[2]), "r"(a[3]),
          "r"(b[0]), "r"(b[1]));
}

extern "C" __global__ void __launch_bounds__(256, 1)
moelb_kernel(const float* __restrict__ x,
             const float* __restrict__ W,
             float* __restrict__ out)
{
    extern __shared__ float smem[];
    float* Xs = smem;              // [128][128], col XOR-swizzled
    float* Ws = smem + BM * RANK;  // [128][128], col XOR-swizzled

    const int tid    = threadIdx.x;
    const int warpId = tid >> 5;
    const int lane   = tid & 31;
    const int g      = lane >> 2;   // groupID (row within fragment)
    const int tig    = lane & 3;    // thread-in-group (col within fragment)

    const int e    = blockIdx.z;
    const int tOff = blockIdx.x * BM;
    const int nOff = blockIdx.y * BN;

    // ---- Load X tile [128 rows x 128 cols], row stride = EXPERTS*RANK floats ----
    {
        const float4* x4 = reinterpret_cast<const float4*>(x);
        const int rowStride4 = (EXPERTS * RANK) / 4;  // 256
        #pragma unroll
        for (int p = 0; p < 16; ++p) {
            int row = p * 8 + warpId;                 // one full 512B row per warp
            float4 v = x4[(size_t)(tOff + row) * rowStride4 + e * (RANK / 4) + lane];
            float4 t;
            t.x = tf32r(v.x); t.y = tf32r(v.y); t.z = tf32r(v.z); t.w = tf32r(v.w);
            int col = (lane * 4) ^ (4 * (row & 7));   // XOR swizzle, keeps 16B alignment
            *reinterpret_cast<float4*>(&Xs[row * RANK + col]) = t;
        }
    }

    // ---- Load W tile: contiguous 64KB block W[e][nOff:nOff+128][0:128] ----
    {
        const float4* w4 = reinterpret_cast<const float4*>(W)
                         + (size_t)e * (OUTF * (RANK / 4))
                         + (size_t)nOff * (RANK / 4);
        #pragma unroll
        for (int p = 0; p < 16; ++p) {
            int idx = p * 256 + tid;
            int row = idx >> 5;          // 32 float4 per row
            int v   = idx & 31;
            float4 q = w4[idx];
            float4 t;
            t.x = tf32r(q.x); t.y = tf32r(q.y); t.z = tf32r(q.z); t.w = tf32r(q.w);
            int col = (v * 4) ^ (4 * (row & 7));
            *reinterpret_cast<float4*>(&Ws[row * RANK + col]) = t;
        }
    }

    __syncthreads();

    const int mW = (warpId >> 1) * 32;  // warp M offset (4 warps over M)
    const int nW = (warpId & 1) * 64;   // warp N offset (2 warps over N)
    const int sk = 4 * g;               // swizzle term: every fragment row has (row&7)==g

    float c[2][8][4];
    #pragma unroll
    for (int mt = 0; mt < 2; ++mt)
        #pragma unroll
        for (int nt = 0; nt < 8; ++nt)
            #pragma unroll
            for (int i = 0; i < 4; ++i)
                c[mt][nt][i] = 0.0f;

    #pragma unroll
    for (int k0 = 0; k0 < RANK; k0 += 8) {
        // swizzled column offsets (loop-variant part; row*128 bases hoist)
        const int o1 = ((k0    ) ^ sk) + tig;
        const int o2 = ((k0 + 4) ^ sk) + tig;

        uint32_t a[2][4];
        #pragma unroll
        for (int mt = 0; mt < 2; ++mt) {
            int r0 = mW + mt * 16 + g;
            a[mt][0] = __float_as_uint(Xs[(r0    ) * RANK + o1]);
            a[mt][1] = __float_as_uint(Xs[(r0 + 8) * RANK + o1]);
            a[mt][2] = __float_as_uint(Xs[(r0    ) * RANK + o2]);
            a[mt][3] = __float_as_uint(Xs[(r0 + 8) * RANK + o2]);
        }
        uint32_t b[8][2];
        #pragma unroll
        for (int nt = 0; nt < 8; ++nt) {
            int n = nW + nt * 8 + g;
            b[nt][0] = __float_as_uint(Ws[n * RANK + o1]);
            b[nt][1] = __float_as_uint(Ws[n * RANK + o2]);
        }
        #pragma unroll
        for (int mt = 0; mt < 2; ++mt)
            #pragma unroll
            for (int nt = 0; nt < 8; ++nt)
                mma_tf32(c[mt][nt], a[mt], b[nt]);
    }

    // ---- Epilogue: out[t, e, o] ----
    #pragma unroll
    for (int mt = 0; mt < 2; ++mt) {
        #pragma unroll
        for (int nt = 0; nt < 8; ++nt) {
            int t0 = tOff + mW + mt * 16 + g;
            int o0 = nOff + nW + nt * 8 + 2 * tig;
            float* p0 = out + ((size_t)t0 * EXPERTS + e) * OUTF + o0;
            float* p1 = out + ((size_t)(t0 + 8) * EXPERTS + e) * OUTF + o0;
            float2 v0 = make_float2(c[mt][nt][0], c[mt][nt][1]);
            float2 v1 = make_float2(c[mt][nt][2], c[mt][nt][3]);
            *reinterpret_cast<float2*>(p0) = v0;
            *reinterpret_cast<float2*>(p1) = v1;
        }
    }
}

extern "C" void kernel_launch(void* const* d_in, const int* in_sizes, int n_in,
                              void* d_out, int out_size)
{
    const float* x = (const float*)d_in[0];
    const float* W = (const float*)d_in[1];
    float* out = (float*)d_out;

    const int T = in_sizes[0] / (EXPERTS * RANK);   // tokens

    const int smemBytes = 2 * BM * RANK * sizeof(float);  // 128 KB
    cudaFuncSetAttribute(moelb_kernel,
                         cudaFuncAttributeMaxDynamicSharedMemorySize, smemBytes);

    dim3 grid(T / BM, OUTF / BN, EXPERTS);
    dim3 block(256);
    moelb_kernel<<<grid, block, smemBytes>>>(x, W, out);
}

// round 2
// speedup vs baseline: 1.0040x; 1.0040x over previous
#include <cuda_runtime.h>
#include <cstdint>
#include <cstddef>

// MOELinearB: out[t,e,o] = sum_r x[t, e*128+r] * W[e,o,r]
// x: [T, 8*128] fp32, W: [8, 4096, 128] fp32, out: [T, 8, 4096] fp32
//
// Per-expert GEMM: M=T (8192), N=4096, K=128.
// CTA tile: 128(M) x 128(N), full K=128 in smem (single-shot, no k-pipeline).
// 8 warps = 4(M) x 2(N); warp tile 32x64 via mma.sync.m16n8k8 TF32.

#define EXPERTS 8
#define RANK    128
#define OUTF    4096
#define BM      128
#define BN      128

__device__ __forceinline__ float tf32r(float f) {
    uint32_t u;
    asm("cvt.rna.tf32.f32 %0, %1;" : "=r"(u) : "f"(f));
    return __uint_as_float(u);
}

__device__ __forceinline__ void mma_tf32(float c[4], const uint32_t a[4], const uint32_t b[2]) {
    asm volatile(
        "mma.sync.aligned.m16n8k8.row.col.f32.tf32.tf32.f32 "
        "{%0,%1,%2,%3}, {%4,%5,%6,%7}, {%8,%9}, {%0,%1,%2,%3};"
        : "+f"(c[0]), "+f"(c[1]), "+f"(c[2]), "+f"(c[3])
        : "r"(a[0]), "r"(a[1]), "r"(a[2]), "r"(a[3]),
          "r"(b[0]), "r"(b[1]));
}

extern "C" __global__ void __launch_bounds__(256, 1)
moelb_kernel(const float* __restrict__ x,
             const float* __restrict__ W,
             float* __restrict__ out)
{
    extern __shared__ float smem[];
    float* Xs = smem;              // [128][128], col XOR-swizzled
    float* Ws = smem + BM * RANK;  // [128][128], col XOR-swizzled

    const int tid    = threadIdx.x;
    const int warpId = tid >> 5;
    const int lane   = tid & 31;
    const int g      = lane >> 2;   // groupID (row within fragment)
    const int tig    = lane & 3;    // thread-in-group (col within fragment)

    const int e    = blockIdx.z;
    const int tOff = blockIdx.x * BM;
    const int nOff = blockIdx.y * BN;

    // ---- Load X tile [128 rows x 128 cols], row stride = EXPERTS*RANK floats ----
    {
        const float4* x4 = reinterpret_cast<const float4*>(x);
        const int rowStride4 = (EXPERTS * RANK) / 4;  // 256
        #pragma unroll
        for (int p = 0; p < 16; ++p) {
            int row = p * 8 + warpId;                 // one full 512B row per warp
            float4 v = x4[(size_t)(tOff + row) * rowStride4 + e * (RANK / 4) + lane];
            float4 t;
            t.x = tf32r(v.x); t.y = tf32r(v.y); t.z = tf32r(v.z); t.w = tf32r(v.w);
            int col = (lane * 4) ^ (4 * (row & 7));   // XOR swizzle, keeps 16B alignment
            *reinterpret_cast<float4*>(&Xs[row * RANK + col]) = t;
        }
    }

    // ---- Load W tile: contiguous 64KB block W[e][nOff:nOff+128][0:128] ----
    {
        const float4* w4 = reinterpret_cast<const float4*>(W)
                         + (size_t)e * (OUTF * (RANK / 4))
                         + (size_t)nOff * (RANK / 4);
        #pragma unroll
        for (int p = 0; p < 16; ++p) {
            int idx = p * 256 + tid;
            int row = idx >> 5;          // 32 float4 per row
            int v   = idx & 31;
            float4 q = w4[idx];
            float4 t;
            t.x = tf32r(q.x); t.y = tf32r(q.y); t.z = tf32r(q.z); t.w = tf32r(q.w);
            int col = (v * 4) ^ (4 * (row & 7));
            *reinterpret_cast<float4*>(&Ws[row * RANK + col]) = t;
        }
    }

    __syncthreads();

    const int mW = (warpId >> 1) * 32;  // warp M offset (4 warps over M)
    const int nW = (warpId & 1) * 64;   // warp N offset (2 warps over N)
    const int sk = 4 * g;               // swizzle term: every fragment row has (row&7)==g

    float c[2][8][4];
    #pragma unroll
    for (int mt = 0; mt < 2; ++mt)
        #pragma unroll
        for (int nt = 0; nt < 8; ++nt)
            #pragma unroll
            for (int i = 0; i < 4; ++i)
                c[mt][nt][i] = 0.0f;

    #pragma unroll
    for (int k0 = 0; k0 < RANK; k0 += 8) {
        // swizzled column offsets (loop-variant part; row*128 bases hoist)
        const int o1 = ((k0    ) ^ sk) + tig;
        const int o2 = ((k0 + 4) ^ sk) + tig;

        uint32_t a[2][4];
        #pragma unroll
        for (int mt = 0; mt < 2; ++mt) {
            int r0 = mW + mt * 16 + g;
            a[mt][0] = __float_as_uint(Xs[(r0    ) * RANK + o1]);
            a[mt][1] = __float_as_uint(Xs[(r0 + 8) * RANK + o1]);
            a[mt][2] = __float_as_uint(Xs[(r0    ) * RANK + o2]);
            a[mt][3] = __float_as_uint(Xs[(r0 + 8) * RANK + o2]);
        }
        uint32_t b[8][2];
        #pragma unroll
        for (int nt = 0; nt < 8; ++nt) {
            int n = nW + nt * 8 + g;
            b[nt][0] = __float_as_uint(Ws[n * RANK + o1]);
            b[nt][1] = __float_as_uint(Ws[n * RANK + o2]);
        }
        #pragma unroll
        for (int mt = 0; mt < 2; ++mt)
            #pragma unroll
            for (int nt = 0; nt < 8; ++nt)
                mma_tf32(c[mt][nt], a[mt], b[nt]);
    }

    // ---- Epilogue: out[t, e, o] ----
    #pragma unroll
    for (int mt = 0; mt < 2; ++mt) {
        #pragma unroll
        for (int nt = 0; nt < 8; ++nt) {
            int t0 = tOff + mW + mt * 16 + g;
            int o0 = nOff + nW + nt * 8 + 2 * tig;
            float* p0 = out + ((size_t)t0 * EXPERTS + e) * OUTF + o0;
            float* p1 = out + ((size_t)(t0 + 8) * EXPERTS + e) * OUTF + o0;
            float2 v0 = make_float2(c[mt][nt][0], c[mt][nt][1]);
            float2 v1 = make_float2(c[mt][nt][2], c[mt][nt][3]);
            *reinterpret_cast<float2*>(p0) = v0;
            *reinterpret_cast<float2*>(p1) = v1;
        }
    }
}

extern "C" void kernel_launch(void* const* d_in, const int* in_sizes, int n_in,
                              void* d_out, int out_size)
{
    const float* x = (const float*)d_in[0];
    const float* W = (const float*)d_in[1];
    float* out = (float*)d_out;

    const int T = in_sizes[0] / (EXPERTS * RANK);   // tokens

    const int smemBytes = 2 * BM * RANK * sizeof(float);  // 128 KB
    cudaFuncSetAttribute(moelb_kernel,
                         cudaFuncAttributeMaxDynamicSharedMemorySize, smemBytes);

    dim3 grid(T / BM, OUTF / BN, EXPERTS);
    dim3 block(256);
    moelb_kernel<<<grid, block, smemBytes>>>(x, W, out);
}